// round 16
// baseline (speedup 1.0000x reference)
#include <cuda_runtime.h>
#include <cstdint>

// Problem constants
#define BSZ   65536
#define ISZ   512
#define HSZ   128
#define TT    2
#define ESP   2
#define ECM   4
#define ETOT  6

// Fused matrix: C[24][512].  Row c = t*12 + cc; cc 0..5 = logit cols, 6..11 = fe cols.
// Db[24]: per-column bias (logit: bias-part + bg ; fe: b_e . Wt)
#define NC 24
__device__ __align__(16) float g_C[NC * ISZ];
__device__ float g_Db[NC];

// ---------------------------------------------------------------------------
// helpers
// ---------------------------------------------------------------------------
__device__ __forceinline__ uint32_t smem_u32(const void* p) {
    uint32_t a;
    asm("{ .reg .u64 t; cvta.to.shared.u64 t, %1; cvt.u32.u64 %0, t; }"
        : "=r"(a) : "l"(p));
    return a;
}

#define CP_ASYNC16(sm, g) \
    asm volatile("cp.async.cg.shared.global [%0], [%1], 16;" :: "r"(sm), "l"(g))
#define CP_COMMIT() asm volatile("cp.async.commit_group;" ::: "memory")
#define CP_WAIT1()  asm volatile("cp.async.wait_group 1;" ::: "memory")

// packed fp32x2 FMA (Blackwell): d = a*b + d, elementwise on 2 packed floats
#define FMA2(d, a, b) \
    asm("fma.rn.f32x2 %0, %1, %2, %0;" : "+l"(d) : "l"(a), "l"(b))

__device__ __forceinline__ const float* wsel(const float* Wc, const float* Ws,
                                             int t, int ep) {
    return (ep < ESP) ? (Ws + (size_t)(t * ESP + ep) * ISZ * HSZ)
                      : (Wc + (size_t)(ep - ESP) * ISZ * HSZ);
}
__device__ __forceinline__ const float* bselp(const float* bc, const float* bs,
                                              int t, int ep) {
    return (ep < ESP) ? (bs + (t * ESP + ep) * HSZ) : (bc + (ep - ESP) * HSZ);
}

// ---------------------------------------------------------------------------
// Kernel 1: precompute fused matrix (warp per element).
// ---------------------------------------------------------------------------
__global__ void __launch_bounds__(256)
precompute_kernel(const float* __restrict__ Wc, const float* __restrict__ bc,
                  const float* __restrict__ Ws, const float* __restrict__ bs,
                  const float* __restrict__ Wg, const float* __restrict__ bg,
                  const float* __restrict__ Wt)
{
    const int lane = threadIdx.x & 31;
    const int wg   = blockIdx.x * 8 + (threadIdx.x >> 5);

    float s = 0.0f;
    if (wg < NC * ISZ) {
        const int c  = wg >> 9;
        const int i  = wg & 511;
        const int t  = c / 12;
        const int cc = c % 12;
        if (cc < ETOT) {
            #pragma unroll
            for (int ep = 0; ep < ETOT; ep++) {
                const float* W = wsel(Wc, Ws, t, ep);
                #pragma unroll
                for (int h = lane; h < HSZ; h += 32)
                    s += W[(size_t)i * HSZ + h]
                       * Wg[(size_t)t * (ETOT * HSZ * ETOT) + (ep * HSZ + h) * ETOT + cc];
            }
        } else {
            const int e = cc - ETOT;                 // 0..5
            const float* W = wsel(Wc, Ws, t, e);
            #pragma unroll
            for (int h = lane; h < HSZ; h += 32)
                s += W[(size_t)i * HSZ + h] * Wt[t * HSZ + h];
        }
        #pragma unroll
        for (int o = 16; o > 0; o >>= 1) s += __shfl_xor_sync(0xFFFFFFFFu, s, o);
        if (lane == 0) g_C[(size_t)c * ISZ + i] = s;
    } else if (wg < NC * ISZ + NC) {
        const int c  = wg - NC * ISZ;
        const int t  = c / 12;
        const int cc = c % 12;
        if (cc < ETOT) {
            for (int f = lane; f < ETOT * HSZ; f += 32) {
                const int ep = f >> 7, h = f & 127;
                s += bselp(bc, bs, t, ep)[h]
                   * Wg[(size_t)t * (ETOT * HSZ * ETOT) + f * ETOT + cc];
            }
        } else {
            const int e = cc - ETOT;
            for (int h = lane; h < HSZ; h += 32)
                s += bselp(bc, bs, t, e)[h] * Wt[t * HSZ + h];
        }
        #pragma unroll
        for (int o = 16; o > 0; o >>= 1) s += __shfl_xor_sync(0xFFFFFFFFu, s, o);
        if (lane == 0) {
            if (cc < ETOT) s += bg[t * ETOT + cc];
            g_Db[c] = s;
        }
    }
}

// ---------------------------------------------------------------------------
// Kernel 2: main pass — thread per (row-quad, task).
//   Thread (p, t) computes rows row0+p+{0,128,256,384} for task t: 12 dots
//   of 512 each; C fragments reused across 4 rows (C-LDS amortized 4x).
//   CTA: 256 threads = 128 quads x 2 tasks -> 512 rows.  Grid 128 (1 wave).
//   3-stage cp.async pipeline, one __syncthreads per chunk.
// SMEM: C [24][512] f32 @ 0                 (49152 B)
//       x [3][512 rows][20 floats] @ 49152  (3 x 40960 B)
//   total 172032 B -> 1 CTA/SM
// ---------------------------------------------------------------------------
#define NCT      12                   // columns per thread (one task)
#define KCH      16
#define NCHUNK   (ISZ / KCH)          // 32
#define ROWS     512                  // rows per CTA
#define XSTRIDE  20                   // floats per staged row (pad 16 -> 20)
#define XBUF     (ROWS * XSTRIDE * 4) // 40960 B
#define OFF_X    (NC * ISZ * 4)       // 49152
#define SMEM_MAIN (OFF_X + 3 * XBUF)  // 172032

__device__ __forceinline__ void load_chunk(uint32_t xb, const float* x,
                                           int row0, int kc, int tid)
{
    // 512 rows x 16 floats = 2048 x 16B ops, 8 per thread
    #pragma unroll
    for (int k = 0; k < 8; k++) {
        const int idx = tid + k * 256;
        const int r   = idx >> 2;
        const int q   = idx & 3;
        CP_ASYNC16(xb + (uint32_t)(r * XSTRIDE + q * 4) * 4,
                   x + (size_t)(row0 + r) * ISZ + kc * KCH + q * 4);
    }
}

__global__ void __launch_bounds__(256, 1)
main_kernel(const float* __restrict__ x, const float* __restrict__ bt,
            float* __restrict__ out)
{
    extern __shared__ __align__(16) char smem[];
    const uint32_t sb   = smem_u32(smem);
    const int tid  = threadIdx.x;
    const int p    = tid & 127;          // row-quad base
    const int task = tid >> 7;
    const int row0 = blockIdx.x * ROWS;

    // group 0: C (48 KB) + chunk 0;  group 1: chunk 1
    {
        const float4* Cg = (const float4*)g_C;
        #pragma unroll
        for (int k = 0; k < 12; k++) {
            const int idx = tid + k * 256;
            CP_ASYNC16(sb + (uint32_t)idx * 16, Cg + idx);
        }
    }
    load_chunk(sb + OFF_X, x, row0, 0, tid);
    CP_COMMIT();
    load_chunk(sb + OFF_X + XBUF, x, row0, 1, tid);
    CP_COMMIT();

    uint64_t acc[4 * NCT];
    #pragma unroll
    for (int c = 0; c < 4 * NCT; c++) acc[c] = 0ull;

    // this thread's task-half of C: 12 rows starting at row task*12
    const char* cbase = smem + (size_t)task * (NCT * ISZ * 4);

    int slot = 0, nslot = 2;             // compute slot, next-load slot
    for (int kc = 0; kc < NCHUNK; kc++) {
        CP_WAIT1();          // chunk kc landed (local view)
        __syncthreads();     // all threads' chunk-kc data visible; all done kc-1
        if (kc + 2 < NCHUNK) {
            load_chunk(sb + OFF_X + nslot * XBUF, x, row0, kc + 2, tid);
            CP_COMMIT();
        }

        const char* xb = smem + OFF_X + slot * XBUF;
        const char* ck = cbase + kc * (KCH * 4);

        #pragma unroll
        for (int h = 0; h < 2; h++) {    // two 8-k halves of the chunk
            ulonglong2 xv[4][2];
            #pragma unroll
            for (int r = 0; r < 4; r++) {
                const ulonglong2* xr =
                    (const ulonglong2*)(xb + (p + r * 128) * (XSTRIDE * 4) + h * 32);
                xv[r][0] = xr[0];
                xv[r][1] = xr[1];
            }
            #pragma unroll
            for (int c = 0; c < NCT; c++) {
                const ulonglong2* cp =
                    (const ulonglong2*)(ck + (size_t)c * (ISZ * 4) + h * 32);
                const ulonglong2 q0 = cp[0], q1 = cp[1];
                #pragma unroll
                for (int r = 0; r < 4; r++) {
                    FMA2(acc[r * NCT + c], xv[r][0].x, q0.x);
                    FMA2(acc[r * NCT + c], xv[r][0].y, q0.y);
                    FMA2(acc[r * NCT + c], xv[r][1].x, q1.x);
                    FMA2(acc[r * NCT + c], xv[r][1].y, q1.y);
                }
            }
        }
        slot  = (slot  == 2) ? 0 : slot  + 1;
        nslot = (nslot == 2) ? 0 : nslot + 1;
    }

    // tail: fold pairs, add bias, per-thread softmax + combine (own task)
    const float btv = __ldg(&bt[task]);
    #pragma unroll
    for (int r = 0; r < 4; r++) {
        float pv[NCT];
        #pragma unroll
        for (int c = 0; c < NCT; c++) {
            const uint64_t a = acc[r * NCT + c];
            const float lo = __uint_as_float((uint32_t)a);
            const float hi = __uint_as_float((uint32_t)(a >> 32));
            pv[c] = lo + hi + __ldg(&g_Db[task * NCT + c]);
        }
        float m = -1e30f;
        #pragma unroll
        for (int oe = 0; oe < ETOT; oe++) m = fmaxf(m, pv[oe]);
        float den = 0.0f, num = 0.0f;
        #pragma unroll
        for (int oe = 0; oe < ETOT; oe++) {
            const float w = __expf(pv[oe] - m);
            den += w;
            num += w * pv[ETOT + oe];
        }
        out[(size_t)task * BSZ + row0 + p + r * 128] = num / den + btv;
    }
}

// ---------------------------------------------------------------------------
// Launch
// ---------------------------------------------------------------------------
extern "C" void kernel_launch(void* const* d_in, const int* in_sizes, int n_in,
                              void* d_out, int out_size)
{
    (void)in_sizes; (void)n_in; (void)out_size;
    const float* x  = (const float*)d_in[0];
    const float* Wc = (const float*)d_in[1];
    const float* bc = (const float*)d_in[2];
    const float* Ws = (const float*)d_in[3];
    const float* bs = (const float*)d_in[4];
    const float* Wg = (const float*)d_in[5];
    const float* bg = (const float*)d_in[6];
    const float* Wt = (const float*)d_in[7];
    const float* bt = (const float*)d_in[8];
    float* out = (float*)d_out;

    cudaFuncSetAttribute(main_kernel,
                         cudaFuncAttributeMaxDynamicSharedMemorySize, SMEM_MAIN);

    const int njobs = NC * ISZ + NC;                  // 12312 warp-jobs
    precompute_kernel<<<(njobs + 7) / 8, 256>>>(Wc, bc, Ws, bs, Wg, bg, Wt);

    main_kernel<<<BSZ / ROWS, 256, SMEM_MAIN>>>(x, bt, out);
}

// round 17
// speedup vs baseline: 1.7411x; 1.7411x over previous
#include <cuda_runtime.h>
#include <cstdint>

// Problem constants
#define BSZ   65536
#define ISZ   512
#define HSZ   128
#define TT    2
#define ESP   2
#define ECM   4
#define ETOT  6

// Fused matrix: C[24][512] (tf32-rounded fp32).  Row c = t*12 + cc;
//   cc 0..5 = logit cols, 6..11 = fe cols.
// Db[24]: per-column bias (logit: bias-part + bg ; fe: b_e . Wt), fp32.
#define NC 24
__device__ __align__(16) float g_C[NC * ISZ];
__device__ float g_Db[NC];

// ---------------------------------------------------------------------------
// helpers
// ---------------------------------------------------------------------------
__device__ __forceinline__ uint32_t smem_u32(const void* p) {
    uint32_t a;
    asm("{ .reg .u64 t; cvta.to.shared.u64 t, %1; cvt.u32.u64 %0, t; }"
        : "=r"(a) : "l"(p));
    return a;
}

__device__ __forceinline__ float to_tf32(float x) {
    uint32_t u;
    asm("cvt.rna.tf32.f32 %0, %1;" : "=r"(u) : "f"(x));
    return __uint_as_float(u);
}

#define CP_ASYNC16(sm, g) \
    asm volatile("cp.async.cg.shared.global [%0], [%1], 16;" :: "r"(sm), "l"(g))
#define CP_COMMIT() asm volatile("cp.async.commit_group;" ::: "memory")
#define CP_WAIT1()  asm volatile("cp.async.wait_group 1;" ::: "memory")
#define CP_WAIT0()  asm volatile("cp.async.wait_group 0;" ::: "memory")

// m16n8k8 tf32 mma (validated in round 4)
__device__ __forceinline__ void mma_tf32(float* c, const uint32_t* a, const uint32_t* b) {
    asm volatile(
        "mma.sync.aligned.m16n8k8.row.col.f32.tf32.tf32.f32 "
        "{%0,%1,%2,%3}, {%4,%5,%6,%7}, {%8,%9}, {%0,%1,%2,%3};\n"
        : "+f"(c[0]), "+f"(c[1]), "+f"(c[2]), "+f"(c[3])
        : "r"(a[0]), "r"(a[1]), "r"(a[2]), "r"(a[3]),
          "r"(b[0]), "r"(b[1]));
}

__device__ __forceinline__ const float* wsel(const float* Wc, const float* Ws,
                                             int t, int ep) {
    return (ep < ESP) ? (Ws + (size_t)(t * ESP + ep) * ISZ * HSZ)
                      : (Wc + (size_t)(ep - ESP) * ISZ * HSZ);
}
__device__ __forceinline__ const float* bselp(const float* bc, const float* bs,
                                              int t, int ep) {
    return (ep < ESP) ? (bs + (t * ESP + ep) * HSZ) : (bc + (ep - ESP) * HSZ);
}

// ---------------------------------------------------------------------------
// Kernel 1: precompute fused matrix (warp per element).  C stored tf32-rounded.
// ---------------------------------------------------------------------------
__global__ void __launch_bounds__(256)
precompute_kernel(const float* __restrict__ Wc, const float* __restrict__ bc,
                  const float* __restrict__ Ws, const float* __restrict__ bs,
                  const float* __restrict__ Wg, const float* __restrict__ bg,
                  const float* __restrict__ Wt)
{
    const int lane = threadIdx.x & 31;
    const int wg   = blockIdx.x * 8 + (threadIdx.x >> 5);

    float s = 0.0f;
    if (wg < NC * ISZ) {
        const int c  = wg >> 9;
        const int i  = wg & 511;
        const int t  = c / 12;
        const int cc = c % 12;
        if (cc < ETOT) {
            #pragma unroll
            for (int ep = 0; ep < ETOT; ep++) {
                const float* W = wsel(Wc, Ws, t, ep);
                #pragma unroll
                for (int h = lane; h < HSZ; h += 32)
                    s += W[(size_t)i * HSZ + h]
                       * Wg[(size_t)t * (ETOT * HSZ * ETOT) + (ep * HSZ + h) * ETOT + cc];
            }
        } else {
            const int e = cc - ETOT;                 // 0..5
            const float* W = wsel(Wc, Ws, t, e);
            #pragma unroll
            for (int h = lane; h < HSZ; h += 32)
                s += W[(size_t)i * HSZ + h] * Wt[t * HSZ + h];
        }
        #pragma unroll
        for (int o = 16; o > 0; o >>= 1) s += __shfl_xor_sync(0xFFFFFFFFu, s, o);
        if (lane == 0) g_C[(size_t)c * ISZ + i] = to_tf32(s);
    } else if (wg < NC * ISZ + NC) {
        const int c  = wg - NC * ISZ;
        const int t  = c / 12;
        const int cc = c % 12;
        if (cc < ETOT) {
            for (int f = lane; f < ETOT * HSZ; f += 32) {
                const int ep = f >> 7, h = f & 127;
                s += bselp(bc, bs, t, ep)[h]
                   * Wg[(size_t)t * (ETOT * HSZ * ETOT) + f * ETOT + cc];
            }
        } else {
            const int e = cc - ETOT;
            for (int h = lane; h < HSZ; h += 32)
                s += bselp(bc, bs, t, e)[h] * Wt[t * HSZ + h];
        }
        #pragma unroll
        for (int o = 16; o > 0; o >>= 1) s += __shfl_xor_sync(0xFFFFFFFFu, s, o);
        if (lane == 0) {
            if (cc < ETOT) s += bg[t * ETOT + cc];
            g_Db[c] = s;
        }
    }
}

// ---------------------------------------------------------------------------
// Kernel 2: main pass — tensor-core P = X . C^T, then per-thread softmax.
//   CTA 256 thr / 8 warps, 128 rows; warp w owns rows [w*16, w*16+16).
//   3 n-tiles of 8 cols (24 total), k = 512 in 16 chunks of 32.
// SMEM: C  [24][516] f32 @ 0      (49536 B)   (padded: +4 -> conflict-free frags)
//       x  [2][128][36] @ 49536   (2 x 18432) (rows padded 32 -> 36)
//       P  [128][26]   @ 86400    (13312 B)
//   total 99712 B -> 2 CTAs/SM
// ---------------------------------------------------------------------------
#define KCH      32
#define NCHUNK   (ISZ / KCH)          // 16
#define ROWS     128                  // rows per CTA
#define CSTRIDE  516                  // C row stride (floats)
#define XSTRIDE  36                   // x row stride (floats)
#define PSTRIDE  26                   // P row stride (floats)
#define OFF_X    (NC * CSTRIDE * 4)   // 49536
#define XBUF     (ROWS * XSTRIDE * 4) // 18432
#define OFF_P    (OFF_X + 2 * XBUF)   // 86400
#define SMEM_MAIN (OFF_P + ROWS * PSTRIDE * 4)  // 99712

__device__ __forceinline__ void load_chunk(uint32_t xb, const float* x,
                                           int row0, int kc, int tid)
{
    // 128 rows x 32 floats = 1024 x 16B ops, 4 per thread
    #pragma unroll
    for (int k = 0; k < 4; k++) {
        const int idx = tid + k * 256;
        const int r   = idx >> 3;
        const int q   = idx & 7;
        CP_ASYNC16(xb + (uint32_t)(r * (XSTRIDE * 4) + q * 16),
                   x + (size_t)(row0 + r) * ISZ + kc * KCH + q * 4);
    }
}

__global__ void __launch_bounds__(256, 2)
main_kernel(const float* __restrict__ x, const float* __restrict__ bt,
            float* __restrict__ out)
{
    extern __shared__ __align__(16) char smem[];
    const uint32_t sb = smem_u32(smem);
    const int tid   = threadIdx.x;
    const int wid   = tid >> 5;
    const int lane  = tid & 31;
    const int group = lane >> 2;      // 0..7
    const int tig   = lane & 3;       // 0..3
    const int row0  = blockIdx.x * ROWS;

    // group 0: C (48 KB, tf32-rounded) + chunk 0
    {
        const float4* Cg = (const float4*)g_C;
        #pragma unroll
        for (int k = 0; k < 12; k++) {
            const int idx = tid + k * 256;
            const int n   = idx >> 7;       // C row
            const int q   = idx & 127;      // 16B unit within row
            CP_ASYNC16(sb + (uint32_t)(n * (CSTRIDE * 4) + q * 16),
                       (const float*)Cg + (size_t)n * ISZ + q * 4);
        }
    }
    load_chunk(sb + OFF_X, x, row0, 0, tid);
    CP_COMMIT();

    float acc[3][4];
    #pragma unroll
    for (int nt = 0; nt < 3; nt++)
        #pragma unroll
        for (int r = 0; r < 4; r++) acc[nt][r] = 0.0f;

    const float* cs = (const float*)smem;                 // C [24][516]
    const int r0 = wid * 16 + group;                      // local row (and +8)

    for (int kc = 0; kc < NCHUNK; kc++) {
        const int buf = kc & 1;
        if (kc + 1 < NCHUNK) {
            load_chunk(sb + OFF_X + (buf ^ 1) * XBUF, x, row0, kc + 1, tid);
            CP_COMMIT();
            CP_WAIT1();
        } else {
            CP_WAIT0();
        }
        __syncthreads();     // chunk kc (and C on kc==0) visible to all

        const float* xs = (const float*)(smem + OFF_X + buf * XBUF);

        #pragma unroll
        for (int kk = 0; kk < KCH; kk += 8) {
            const int kg = kc * KCH + kk;     // global k for C indexing
            uint32_t afr[4];
            afr[0] = __float_as_uint(to_tf32(xs[(r0    ) * XSTRIDE + kk + tig    ]));
            afr[1] = __float_as_uint(to_tf32(xs[(r0 + 8) * XSTRIDE + kk + tig    ]));
            afr[2] = __float_as_uint(to_tf32(xs[(r0    ) * XSTRIDE + kk + tig + 4]));
            afr[3] = __float_as_uint(to_tf32(xs[(r0 + 8) * XSTRIDE + kk + tig + 4]));
            #pragma unroll
            for (int nt = 0; nt < 3; nt++) {
                const int cn = nt * 8 + group;
                uint32_t bfr[2];
                bfr[0] = __float_as_uint(cs[cn * CSTRIDE + kg + tig    ]);
                bfr[1] = __float_as_uint(cs[cn * CSTRIDE + kg + tig + 4]);
                mma_tf32(acc[nt], afr, bfr);
            }
        }
        __syncthreads();     // all warps done with buf before it is reloaded
    }

    // epilogue: accumulators -> P smem
    float* Ps = (float*)(smem + OFF_P);
    #pragma unroll
    for (int nt = 0; nt < 3; nt++) {
        const int c = nt * 8 + tig * 2;
        *(float2*)&Ps[(r0    ) * PSTRIDE + c] = make_float2(acc[nt][0], acc[nt][1]);
        *(float2*)&Ps[(r0 + 8) * PSTRIDE + c] = make_float2(acc[nt][2], acc[nt][3]);
    }
    __syncthreads();

    // thread t: (row = t&127, task = t>>7): softmax over 6 logits, combine
    {
        const int row  = tid & 127;
        const int task = tid >> 7;
        float pv[12];
        #pragma unroll
        for (int c = 0; c < 12; c++)
            pv[c] = Ps[row * PSTRIDE + task * 12 + c] + __ldg(&g_Db[task * 12 + c]);

        float m = -1e30f;
        #pragma unroll
        for (int oe = 0; oe < ETOT; oe++) m = fmaxf(m, pv[oe]);
        float den = 0.0f, num = 0.0f;
        #pragma unroll
        for (int oe = 0; oe < ETOT; oe++) {
            const float w = __expf(pv[oe] - m);
            den += w;
            num += w * pv[ETOT + oe];
        }
        out[(size_t)task * BSZ + row0 + row] = num / den + __ldg(&bt[task]);
    }
}

// ---------------------------------------------------------------------------
// Launch
// ---------------------------------------------------------------------------
extern "C" void kernel_launch(void* const* d_in, const int* in_sizes, int n_in,
                              void* d_out, int out_size)
{
    (void)in_sizes; (void)n_in; (void)out_size;
    const float* x  = (const float*)d_in[0];
    const float* Wc = (const float*)d_in[1];
    const float* bc = (const float*)d_in[2];
    const float* Ws = (const float*)d_in[3];
    const float* bs = (const float*)d_in[4];
    const float* Wg = (const float*)d_in[5];
    const float* bg = (const float*)d_in[6];
    const float* Wt = (const float*)d_in[7];
    const float* bt = (const float*)d_in[8];
    float* out = (float*)d_out;

    cudaFuncSetAttribute(main_kernel,
                         cudaFuncAttributeMaxDynamicSharedMemorySize, SMEM_MAIN);

    const int njobs = NC * ISZ + NC;                  // 12312 warp-jobs
    precompute_kernel<<<(njobs + 7) / 8, 256>>>(Wc, bc, Ws, bs, Wg, bg, Wt);

    main_kernel<<<BSZ / ROWS, 256, SMEM_MAIN>>>(x, bt, out);
}